// round 12
// baseline (speedup 1.0000x reference)
#include <cuda_runtime.h>
#include <cuda_bf16.h>
#include <cstdint>
#include <cstddef>

#define B_   1024
#define S_   100
#define H_   512
#define NU   1000

// ---------------- scratch (static device memory; no allocations) ----------------
__device__ __nv_bfloat16 g_obf[(size_t)B_ * S_ * H_];     // bf16 GRU outputs
__device__ __nv_bfloat16 g_h0[B_ * H_];                   // initial h bf16
__device__ float         g_xp[(size_t)B_ * S_ * 1536];    // x-projection fp32
__device__ __nv_bfloat16 g_wabf[(size_t)NU * H_ * H_];    // Wa bf16
__device__ float         g_R[NU * H_];                    // fp32 Wa row sums
__device__ unsigned char g_wblob[16 * 2 * 4 * 24576];     // GRU/xproj W tiles bf16
__device__ unsigned g_gbarc[8];
__device__ unsigned g_gbarg[8];

// ---------------- helpers ----------------
__device__ __forceinline__ void cpa16(uint32_t s, const void* g) {
    asm volatile("cp.async.cg.shared.global [%0], [%1], 16;\n" :: "r"(s), "l"(g));
}
__device__ __forceinline__ void cp_commit() { asm volatile("cp.async.commit_group;\n"); }
template<int N> __device__ __forceinline__ void cp_wait() {
    asm volatile("cp.async.wait_group %0;\n" :: "n"(N));
}
__device__ __forceinline__ float sigf(float x)  { return 1.0f / (1.0f + __expf(-x)); }
__device__ __forceinline__ float tanhc(float x) { return 1.0f - 2.0f / (__expf(2.0f * x) + 1.0f); }

__device__ __forceinline__ void mma16(float c[4], const uint32_t a[4], const uint32_t b[2]) {
    asm volatile(
        "mma.sync.aligned.m16n8k16.row.col.f32.bf16.bf16.f32 "
        "{%0,%1,%2,%3}, {%4,%5,%6,%7}, {%8,%9}, {%0,%1,%2,%3};\n"
        : "+f"(c[0]), "+f"(c[1]), "+f"(c[2]), "+f"(c[3])
        : "r"(a[0]), "r"(a[1]), "r"(a[2]), "r"(a[3]), "r"(b[0]), "r"(b[1]));
}
__device__ __forceinline__ void ldsm4(uint32_t r[4], uint32_t addr) {
    asm volatile("ldmatrix.sync.aligned.m8n8.x4.shared.b16 {%0,%1,%2,%3}, [%4];"
        : "=r"(r[0]), "=r"(r[1]), "=r"(r[2]), "=r"(r[3]) : "r"(addr));
}
__device__ __forceinline__ uint32_t pack_bf(float x, float y) {
    __nv_bfloat162 p = __floats2bfloat162_rn(x, y);
    return *(uint32_t*)&p;
}

// =====================================================================
// Prep kernels
// =====================================================================
__global__ void prep_h0(const float4* __restrict__ Hd) {
    int i = blockIdx.x * 1024 + threadIdx.x;
    if (i < B_ * H_ / 4) {
        float4 v = Hd[i];
        *(uint2*)&g_h0[i * 4] = make_uint2(pack_bf(v.x, v.y), pack_bf(v.z, v.w));
    }
}
// W blobs: [ct 16][phase 2][chunk 4] of 96 rows x 128 k bf16 (row-major 256B rows)
__global__ void prep_w(const float* __restrict__ Whh, const float* __restrict__ Wih) {
    size_t idx = (size_t)blockIdx.x * 1024 + threadIdx.x;
    if (idx >= (size_t)16 * 2 * 4 * 96 * 128) return;
    int k  = (int)(idx & 127);
    size_t i2 = idx >> 7;
    int r = (int)(i2 % 96); size_t i3 = i2 / 96;
    int c = (int)(i3 & 3);
    size_t i4 = i3 >> 2;
    int p  = (int)(i4 & 1);
    int ct = (int)(i4 >> 1);
    const float* W = p ? Wih : Whh;
    int grow = (r >> 5) * 512 + ct * 32 + (r & 31);
    float v = W[(size_t)grow * 512 + c * 128 + k];
    size_t blob = ((size_t)(ct * 2 + p) * 4 + c) * 24576;
    *(__nv_bfloat16*)(g_wblob + blob + (size_t)r * 256 + k * 2) = __float2bfloat16(v);
}

// =====================================================================
// xproj v2: one CTA per 64-row m-tile, A resident in smem, loops ct=0..15.
// 256 threads, warp tile 16 rows x 48 cols (warps 4m x 2n).
// Wa-prep CTAs fused (bid >= 1600).
// =====================================================================
#define XP_CTAS 1600
#define XPREP   744
#define XA_CH   17408          // one K=128 A chunk: 64 x 272B
#define XB_OFF  69632          // 4 * XA_CH
#define XB_STG  26112          // 96 x 272B
#define XSM     (XB_OFF + 2 * XB_STG)   // 121856

__global__ void __launch_bounds__(256)
xproj_kernel(const float* __restrict__ reps, const float* __restrict__ Wa) {
    const int bid = blockIdx.x;
    const int tid = threadIdx.x;

    if (bid >= XP_CTAS) {
        // ---------- fused Wa prep (fp32 -> bf16 + row sums) ----------
        int wp = tid >> 5, lane = tid & 31;
        for (int gw = (bid - XP_CTAS) * 8 + wp; gw < NU * 512; gw += XPREP * 8) {
            const float* src = Wa + (size_t)gw * 512;
            __nv_bfloat16* dst = g_wabf + (size_t)gw * 512;
            float s = 0.0f;
#pragma unroll
            for (int i = 0; i < 4; i++) {
                float4 v = *(const float4*)&src[(lane + i * 32) * 4];
                s += v.x + v.y + v.z + v.w;
                *(uint2*)&dst[(lane + i * 32) * 4] =
                    make_uint2(pack_bf(v.x, v.y), pack_bf(v.z, v.w));
            }
#pragma unroll
            for (int off = 16; off > 0; off >>= 1) s += __shfl_xor_sync(0xffffffffu, s, off);
            if (lane == 0) g_R[gw] = s;
        }
        return;
    }

    // ---------- xproj ----------
    extern __shared__ unsigned char dsm[];
    const uint32_t smb = (uint32_t)__cvta_generic_to_shared(dsm);
    const int m0 = bid * 64;
    const int l  = tid & 31;
    const int w  = tid >> 5;
    const int g  = l >> 2;
    const int tg = l & 3;
    const int wm = (w >> 1) * 16;          // m-warp row base (4 m-warps)
    const int wn = (w & 1) * 48;           // n-warp col base (2 n-warps)
    const uint32_t loff = (uint32_t)((((l >> 3) & 1) * 8 + (l & 7)) * 272 + (l >> 4) * 16);

    // B loader slots: 1536 16B-units per stage / 256 thr = 6  (FIXED: full 256B rows)
    uint32_t bro[6], bso[6];
#pragma unroll
    for (int i = 0; i < 6; i++) {
        int u = tid + i * 256;             // < 1536
        bro[i] = (uint32_t)((u >> 4) * 272 + (u & 15) * 16);
        bso[i] = (uint32_t)u * 16;         // blob rows contiguous 256B
    }
    auto issueB = [&](int cg) {
        int ct = cg >> 2, c = cg & 3;
        const unsigned char* blob = g_wblob + ((size_t)(ct * 2 + 1) * 4 + c) * 24576;
        uint32_t base = smb + XB_OFF + (uint32_t)(cg & 1) * XB_STG;
#pragma unroll
        for (int i = 0; i < 6; i++) cpa16(base + bro[i], blob + bso[i]);
        cp_commit();
    };

    issueB(0); issueB(1);

    // A fill: 64 rows x 512 fp32 -> bf16 chunked (once per CTA)
#pragma unroll
    for (int i = 0; i < 32; i++) {
        int u = tid + i * 256;               // < 8192
        int r = u >> 7, k = (u & 127) * 4;
        float4 v = *(const float4*)&reps[(size_t)(m0 + r) * 512 + k];
        *(uint2*)(dsm + (k >> 7) * XA_CH + r * 272 + (k & 127) * 2) =
            make_uint2(pack_bf(v.x, v.y), pack_bf(v.z, v.w));
    }
    __syncthreads();

    float acc[6][4];
    for (int cg = 0; cg < 64; cg++) {
        int ct = cg >> 2, c = cg & 3;
        if (c == 0) {
#pragma unroll
            for (int i = 0; i < 6; i++)
#pragma unroll
                for (int j = 0; j < 4; j++) acc[i][j] = 0.0f;
        }
        if (cg < 63) cp_wait<1>(); else cp_wait<0>();
        __syncthreads();
        uint32_t Ab = smb + (uint32_t)c * XA_CH + (uint32_t)wm * 272 + loff;
        uint32_t Bb = smb + XB_OFF + (uint32_t)(cg & 1) * XB_STG + (uint32_t)wn * 272 + loff;
#pragma unroll
        for (int kk = 0; kk < 8; kk++) {
            uint32_t kb = (uint32_t)kk * 32;
            uint32_t a[4]; ldsm4(a, Ab + kb);
#pragma unroll
            for (int q = 0; q < 3; q++) {
                uint32_t r4[4]; ldsm4(r4, Bb + (uint32_t)(q * 16) * 272 + kb);
                uint32_t b0f[2] = { r4[0], r4[2] }, b1f[2] = { r4[1], r4[3] };
                mma16(acc[2 * q], a, b0f);
                mma16(acc[2 * q + 1], a, b1f);
            }
        }
        __syncthreads();
        if (cg + 2 < 64) issueB(cg + 2);
        if (c == 3) {
#pragma unroll
            for (int f = 0; f < 6; f++) {
                int col = wn + 8 * f + 2 * tg;
                size_t m = (size_t)(m0 + wm + g);
                *(float2*)&g_xp[(m * 16 + ct) * 96 + col] =
                    make_float2(acc[f][0], acc[f][1]);
                *(float2*)&g_xp[((m + 8) * 16 + ct) * 96 + col] =
                    make_float2(acc[f][2], acc[f][3]);
            }
        }
    }
}

// =====================================================================
// Persistent GRU: 128 CTAs = 8 batch-groups(128 rows) x 16 col-tiles(32 hcols).
// 256 threads, 1 CTA/SM. Whh tile RESIDENT in smem across all 100 steps.
// h_prev in registers; outputs written bf16 only. Warp w owns rows 16w..16w+15.
// =====================================================================
#define GA_STG  34816          // one K=128 A stage: 128 x 272B
#define GB_OFF  69632          // 2 * GA_STG
#define GB_CH   26112          // 96 x 272B
#define GXP_OFF 174080         // GB_OFF + 4 * GB_CH
#define GSM     225280         // GXP_OFF + 128*400

__global__ void __launch_bounds__(256)
gru_kernel(const float* __restrict__ hidden,
           const float* __restrict__ bhh,
           const float* __restrict__ bih) {
    extern __shared__ unsigned char dsm[];
    const uint32_t smb = (uint32_t)__cvta_generic_to_shared(dsm);
    __shared__ float sb[128];

    const int cta  = blockIdx.x;
    const int bg   = cta >> 4;
    const int ct   = cta & 15;
    const int b0   = bg * 128;
    const int col0 = ct * 32;
    const int tid  = threadIdx.x;
    const int l    = tid & 31;
    const int w    = tid >> 5;
    const int g    = l >> 2;
    const int tg   = l & 3;
    const uint32_t loff = (uint32_t)((((l >> 3) & 1) * 8 + (l & 7)) * 272 + (l >> 4) * 16);

    // ---- B (Whh) resident fill: 6144 16B-units / 256 thr = 24  (FIXED: full rows) ----
#pragma unroll
    for (int i = 0; i < 24; i++) {
        int u = tid + i * 256;               // < 6144
        int chunk = u / 1536, rem = u % 1536;
        int rr = rem >> 4, ku = rem & 15;
        const unsigned char* blob = g_wblob + ((size_t)(ct * 2) * 4 + chunk) * 24576;
        *(uint4*)(dsm + GB_OFF + chunk * GB_CH + rr * 272 + ku * 16) =
            *(const uint4*)(blob + rr * 256 + ku * 16);
    }
    if (tid < 32) {
        int jc = col0 + tid;
        sb[tid]      = bih[jc] + bhh[jc];
        sb[32 + tid] = bih[512 + jc] + bhh[512 + jc];
        sb[64 + tid] = bhh[1024 + jc];
        sb[96 + tid] = bih[1024 + jc];
    }
    __syncthreads();

    // loader slot geometry (FIXED: 2048 units per A chunk -> 8 slots)
    int ar2[8], ak2[8];
#pragma unroll
    for (int i = 0; i < 8; i++) {
        int u = tid + i * 256;               // < 2048
        ar2[i] = u >> 4; ak2[i] = u & 15;
    }
    int xpr[12], xpc[12];
#pragma unroll
    for (int i = 0; i < 12; i++) {
        int u = tid + i * 256;               // < 3072
        xpr[i] = u / 24; xpc[i] = u % 24;
    }

    unsigned gen = *((volatile unsigned*)&g_gbarg[bg]);

    // ---- h_prev in registers ----
    float hv[16];
#pragma unroll
    for (int half = 0; half < 2; half++)
#pragma unroll
        for (int q = 0; q < 4; q++) {
            int rr = b0 + 16 * w + g + 8 * half;
            float2 t2 = *(const float2*)&hidden[(size_t)rr * 512 + col0 + 8 * q + 2 * tg];
            hv[half * 8 + q * 2]     = t2.x;
            hv[half * 8 + q * 2 + 1] = t2.y;
        }

    for (int t = 0; t < S_; t++) {
        // xp prefetch (its own group, issued first)
#pragma unroll
        for (int i = 0; i < 12; i++)
            cpa16(smb + GXP_OFF + (uint32_t)(xpr[i] * 400 + xpc[i] * 16),
                  g_xp + (((size_t)(b0 + xpr[i]) * S_ + t) * 16 + ct) * 96 + xpc[i] * 4);
        cp_commit();

        auto issueA = [&](int c) {
            uint32_t base = smb + (uint32_t)(c & 1) * GA_STG;
#pragma unroll
            for (int i = 0; i < 8; i++) {
                const __nv_bfloat16* src = (t == 0)
                    ? g_h0 + (size_t)(b0 + ar2[i]) * 512 + c * 128 + ak2[i] * 8
                    : g_obf + ((size_t)(b0 + ar2[i]) * S_ + (t - 1)) * 512 + c * 128 + ak2[i] * 8;
                cpa16(base + (uint32_t)(ar2[i] * 272 + ak2[i] * 16), src);
            }
            cp_commit();
        };

        float acc[12][4];
#pragma unroll
        for (int i = 0; i < 12; i++)
#pragma unroll
            for (int j = 0; j < 4; j++) acc[i][j] = 0.0f;

        issueA(0); issueA(1);
        for (int c = 0; c < 4; c++) {
            if (c < 3) cp_wait<1>(); else cp_wait<0>();
            __syncthreads();
            uint32_t Ab = smb + (uint32_t)(c & 1) * GA_STG + (uint32_t)(16 * w) * 272 + loff;
            uint32_t Bb = smb + GB_OFF + (uint32_t)c * GB_CH + loff;
#pragma unroll
            for (int kk = 0; kk < 8; kk++) {
                uint32_t kb = (uint32_t)kk * 32;
                uint32_t a[4]; ldsm4(a, Ab + kb);
#pragma unroll
                for (int q = 0; q < 6; q++) {
                    uint32_t r4[4]; ldsm4(r4, Bb + (uint32_t)(q * 16) * 272 + kb);
                    uint32_t b0f[2] = { r4[0], r4[2] }, b1f[2] = { r4[1], r4[3] };
                    mma16(acc[2 * q], a, b0f);
                    mma16(acc[2 * q + 1], a, b1f);
                }
            }
            __syncthreads();
            if (c < 2) issueA(c + 2);
        }

        // ---- in-register gates: frags 0-3 r, 4-7 z, 8-11 nh; x-part from xp smem ----
        const float* xrow0 = (const float*)(dsm + GXP_OFF);
#pragma unroll
        for (int half = 0; half < 2; half++) {
            int lrow = 16 * w + g + 8 * half;
            int rr = b0 + lrow;
            __nv_bfloat16* ob = g_obf + ((size_t)rr * S_ + t) * 512 + col0;
            const float* xr = xrow0 + lrow * 100;
#pragma unroll
            for (int q = 0; q < 4; q++) {
                int j = 8 * q + 2 * tg;
                float2 xr2 = *(const float2*)(xr + j);
                float2 xz2 = *(const float2*)(xr + 32 + j);
                float2 xn2 = *(const float2*)(xr + 64 + j);
                int hvi = half * 8 + q * 2;
                float r0 = sigf(xr2.x + acc[q][2 * half]     + sb[j]);
                float r1 = sigf(xr2.y + acc[q][2 * half + 1] + sb[j + 1]);
                float z0 = sigf(xz2.x + acc[4 + q][2 * half]     + sb[32 + j]);
                float z1 = sigf(xz2.y + acc[4 + q][2 * half + 1] + sb[32 + j + 1]);
                float n0 = tanhc((xn2.x + sb[96 + j])     + r0 * (acc[8 + q][2 * half]     + sb[64 + j]));
                float n1 = tanhc((xn2.y + sb[96 + j + 1]) + r1 * (acc[8 + q][2 * half + 1] + sb[64 + j + 1]));
                float o0 = (1.0f - z0) * n0 + z0 * hv[hvi];
                float o1 = (1.0f - z1) * n1 + z1 * hv[hvi + 1];
                hv[hvi] = o0; hv[hvi + 1] = o1;
                *(uint32_t*)(ob + j) = pack_bf(o0, o1);
            }
        }

        // ---- group barrier (16 CTAs of this batch group) ----
        if (t < S_ - 1) {
            __syncthreads();
            if (tid == 0) {
                unsigned target = gen + 1;
                __threadfence();
                if (atomicAdd(&g_gbarc[bg], 1u) == 15u) {
                    g_gbarc[bg] = 0;
                    __threadfence();
                    atomicExch(&g_gbarg[bg], target);
                } else {
                    while (*((volatile unsigned*)&g_gbarg[bg]) != target) __nanosleep(32);
                    __threadfence();
                }
                gen = target;
            }
            __syncthreads();
        }
    }
}

// =====================================================================
// Attention: A = g_obf (bf16), masked rows fixed up in smem.
// Wa bf16 streamed 4-deep. 8 o-passes of 64 cols. (unchanged, proven)
// =====================================================================
#define A_STRIDE 1040
#define B_STRIDE 144
#define B_STG    9216
#define ATTN_SM  (133120 + 4 * B_STG)

__global__ void __launch_bounds__(256)
attn_kernel(const float* __restrict__ reps,
            const int*   __restrict__ counts,
            const int*   __restrict__ users,
            const float* __restrict__ ba,
            const float* __restrict__ Ws,
            const float* __restrict__ bs,
            float*       __restrict__ outp) {
    extern __shared__ unsigned char dsm[];
    const uint32_t smb = (uint32_t)__cvta_generic_to_shared(dsm);
    __shared__ float scores_s[128];
    __shared__ float wts[S_];
    __shared__ float inv_s;

    const int b   = blockIdx.x;
    const int u   = users[b];
    const int cnt = counts[b];
    const size_t ub = (size_t)u * 512;
    const __nv_bfloat16* wab = g_wabf + (size_t)u * 512 * 512;

    const int tid = threadIdx.x;
    const int l   = tid & 31;
    const int w   = tid >> 5;
    const int g   = l >> 2;
    const int tg  = l & 3;
    const uint32_t loffA = (uint32_t)((((l >> 3) & 1) * 8 + (l & 7)) * A_STRIDE + (l >> 4) * 16);
    const uint32_t loffB = (uint32_t)((((l >> 3) & 1) * 8 + (l & 7)) * B_STRIDE + (l >> 4) * 16);

    int rB[2], kuB[2];
#pragma unroll
    for (int i = 0; i < 2; i++) {
        int uu = tid + i * 256;
        rB[i] = uu >> 3; kuB[i] = uu & 7;
    }
    auto issueB = [&](int gidx) {
        int pass = gidx >> 3, c = gidx & 7;
        uint32_t base = smb + 133120 + (uint32_t)(gidx & 3) * B_STG;
#pragma unroll
        for (int i = 0; i < 2; i++)
            cpa16(base + (uint32_t)(rB[i] * B_STRIDE + kuB[i] * 16),
                  wab + (size_t)(pass * 64 + rB[i]) * 512 + c * 64 + kuB[i] * 8);
        cp_commit();
    };

    issueB(0); issueB(1); issueB(2);

#pragma unroll
    for (int i = 0; i < 25; i++) {
        int uu = tid + i * 256;
        int row = uu >> 6, cu = uu & 63;
        uint4 v = *(const uint4*)&g_obf[((size_t)b * S_ + row) * 512 + cu * 8];
        *(uint4*)(dsm + row * A_STRIDE + cu * 16) = v;
    }
    __syncthreads();
    {
        int nwords = (S_ - cnt) * 256;
        for (int widx = tid; widx < nwords; widx += 256) {
            int row = cnt + (widx >> 8), cw = widx & 255;
            uint32_t* p = (uint32_t*)(dsm + row * A_STRIDE + cw * 4);
            uint32_t pv = *p;
            __nv_bfloat162 bv = *(__nv_bfloat162*)&pv;
            float vx = (__bfloat162float(bv.x) - 1e6f) + 1e6f;
            float vy = (__bfloat162float(bv.y) - 1e6f) + 1e6f;
            *p = pack_bf(vx, vy);
        }
    }
    __syncthreads();

    const bool m0 = (16 * w + g >= cnt);
    const bool m1 = (16 * w + 8 + g >= cnt);
    float pr0 = 0.0f, pr1 = 0.0f;

    for (int pass = 0; pass < 8; pass++) {
        float acc[8][4];
#pragma unroll
        for (int i = 0; i < 8; i++)
#pragma unroll
            for (int j = 0; j < 4; j++) acc[i][j] = 0.0f;

        for (int c = 0; c < 8; c++) {
            int gidx = pass * 8 + c;
            if (gidx < 62) cp_wait<2>();
            else if (gidx == 62) cp_wait<1>();
            else cp_wait<0>();
            __syncthreads();
            uint32_t Ab = smb + (uint32_t)(w * 16) * A_STRIDE + loffA + (uint32_t)(c * 64) * 2;
            uint32_t Bb = smb + 133120 + (uint32_t)(gidx & 3) * B_STG + loffB;
#pragma unroll
            for (int kk = 0; kk < 4; kk++) {
                uint32_t a[4]; ldsm4(a, Ab + (uint32_t)kk * 32);
#pragma unroll
                for (int q = 0; q < 4; q++) {
                    uint32_t r4[4];
                    ldsm4(r4, Bb + (uint32_t)(q * 16) * B_STRIDE + (uint32_t)kk * 32);
                    uint32_t b0f[2] = { r4[0], r4[2] }, b1f[2] = { r4[1], r4[3] };
                    mma16(acc[2 * q], a, b0f);
                    mma16(acc[2 * q + 1], a, b1f);
                }
            }
            __syncthreads();
            if (gidx + 3 < 64) issueB(gidx + 3);
        }

        int o0 = pass * 64;
#pragma unroll
        for (int f = 0; f < 8; f++) {
            int col = o0 + 8 * f + 2 * tg;
            float2 bav = *(const float2*)&ba[ub + col];
            float2 wsv = *(const float2*)&Ws[ub + col];
            float2 Rv  = *(const float2*)&g_R[ub + col];
            float C0 = bav.x - 1e6f * Rv.x;
            float C1 = bav.y - 1e6f * Rv.y;
            pr0 += tanhc(acc[f][0] + (m0 ? C0 : bav.x)) * wsv.x
                 + tanhc(acc[f][1] + (m0 ? C1 : bav.y)) * wsv.y;
            pr1 += tanhc(acc[f][2] + (m1 ? C0 : bav.x)) * wsv.x
                 + tanhc(acc[f][3] + (m1 ? C1 : bav.y)) * wsv.y;
        }
    }

    pr0 += __shfl_xor_sync(0xffffffffu, pr0, 1);
    pr0 += __shfl_xor_sync(0xffffffffu, pr0, 2);
    pr1 += __shfl_xor_sync(0xffffffffu, pr1, 1);
    pr1 += __shfl_xor_sync(0xffffffffu, pr1, 2);
    float bsu = bs[u];
    if (tg == 0) {
        scores_s[16 * w + g]     = pr0 + bsu;
        scores_s[16 * w + 8 + g] = pr1 + bsu;
    }
    __syncthreads();

    if (w == 0) {
        float m = -1e30f;
        for (int s = l; s < S_; s += 32) m = fmaxf(m, scores_s[s]);
#pragma unroll
        for (int off = 16; off > 0; off >>= 1) m = fmaxf(m, __shfl_xor_sync(0xffffffffu, m, off));
        float sum = 0.0f;
        for (int s = l; s < S_; s += 32) {
            float e = __expf(scores_s[s] - m);
            wts[s] = e;
            sum += e;
        }
#pragma unroll
        for (int off = 16; off > 0; off >>= 1) sum += __shfl_xor_sync(0xffffffffu, sum, off);
        if (l == 0) inv_s = 1.0f / sum;
    }
    __syncthreads();

    const float* rb = reps + (size_t)b * S_ * 512;
    float acc0 = 0.0f, acc1 = 0.0f;
    for (int s = 0; s < S_; s++) {
        float wv = wts[s];
        acc0 += wv * rb[(size_t)s * 512 + tid];
        acc1 += wv * rb[(size_t)s * 512 + 256 + tid];
    }
    float inv = inv_s;
    outp[(size_t)b * 512 + tid]       = acc0 * inv;
    outp[(size_t)b * 512 + 256 + tid] = acc1 * inv;
}

// =====================================================================
extern "C" void kernel_launch(void* const* d_in, const int* in_sizes, int n_in,
                              void* d_out, int out_size) {
    (void)in_sizes; (void)n_in; (void)out_size;
    const float* reps   = (const float*)d_in[0];
    const float* hidden = (const float*)d_in[1];
    const int*   counts = (const int*)  d_in[2];
    const int*   users  = (const int*)  d_in[3];
    const float* Wih    = (const float*)d_in[4];
    const float* Whh    = (const float*)d_in[5];
    const float* bih    = (const float*)d_in[6];
    const float* bhh    = (const float*)d_in[7];
    const float* Wa     = (const float*)d_in[8];
    const float* ba     = (const float*)d_in[9];
    const float* Wsc    = (const float*)d_in[10];
    const float* bsc    = (const float*)d_in[11];
    float* outp = (float*)d_out;

    cudaFuncSetAttribute(xproj_kernel, cudaFuncAttributeMaxDynamicSharedMemorySize, XSM);
    cudaFuncSetAttribute(gru_kernel, cudaFuncAttributeMaxDynamicSharedMemorySize, GSM);
    cudaFuncSetAttribute(attn_kernel, cudaFuncAttributeMaxDynamicSharedMemorySize, ATTN_SM);

    prep_h0<<<128, 1024>>>((const float4*)hidden);
    prep_w<<<1536, 1024>>>(Whh, Wih);
    xproj_kernel<<<XP_CTAS + XPREP, 256, XSM>>>(reps, Wa);
    gru_kernel<<<128, 256, GSM>>>(hidden, bhh, bih);
    attn_kernel<<<B_, 256, ATTN_SM>>>(reps, counts, users, ba, Wsc, bsc, outp);
}

// round 13
// speedup vs baseline: 1.4981x; 1.4981x over previous
#include <cuda_runtime.h>
#include <cuda_bf16.h>
#include <cstdint>
#include <cstddef>

#define B_   1024
#define S_   100
#define H_   512
#define NU   1000
#define GRU_CTAS  256
#define PREP_CTAS 744

// ---------------- scratch (static device memory; no allocations) ----------------
__device__ float         g_out[(size_t)B_ * S_ * H_];     // fp32 outputs (own-row recurrence)
__device__ __nv_bfloat16 g_obf[(size_t)B_ * S_ * H_];     // bf16 outputs (cross-CTA A source + attn)
__device__ __nv_bfloat16 g_h0[B_ * H_];                   // initial h bf16
__device__ float         g_xp[(size_t)B_ * S_ * 1536];    // x-projection, per col-tile groups of 96
__device__ __nv_bfloat16 g_wabf[(size_t)NU * H_ * H_];    // Wa bf16
__device__ float         g_R[NU * H_];                    // fp32 Wa row sums
__device__ unsigned char g_wblob[16 * 2 * 4 * 24576];     // GRU/xproj W tiles bf16
__device__ unsigned g_gbarc[16];
__device__ unsigned g_gbarg[16];

// ---------------- helpers ----------------
__device__ __forceinline__ void cpa16(uint32_t s, const void* g) {
    asm volatile("cp.async.cg.shared.global [%0], [%1], 16;\n" :: "r"(s), "l"(g));
}
__device__ __forceinline__ void cp_commit() { asm volatile("cp.async.commit_group;\n"); }
template<int N> __device__ __forceinline__ void cp_wait() {
    asm volatile("cp.async.wait_group %0;\n" :: "n"(N));
}
__device__ __forceinline__ float sigf(float x)  { return 1.0f / (1.0f + __expf(-x)); }
__device__ __forceinline__ float tanhc(float x) { return 1.0f - 2.0f / (__expf(2.0f * x) + 1.0f); }

__device__ __forceinline__ void mma16(float c[4], const uint32_t a[4], const uint32_t b[2]) {
    asm volatile(
        "mma.sync.aligned.m16n8k16.row.col.f32.bf16.bf16.f32 "
        "{%0,%1,%2,%3}, {%4,%5,%6,%7}, {%8,%9}, {%0,%1,%2,%3};\n"
        : "+f"(c[0]), "+f"(c[1]), "+f"(c[2]), "+f"(c[3])
        : "r"(a[0]), "r"(a[1]), "r"(a[2]), "r"(a[3]), "r"(b[0]), "r"(b[1]));
}
__device__ __forceinline__ void ldsm4(uint32_t r[4], uint32_t addr) {
    asm volatile("ldmatrix.sync.aligned.m8n8.x4.shared.b16 {%0,%1,%2,%3}, [%4];"
        : "=r"(r[0]), "=r"(r[1]), "=r"(r[2]), "=r"(r[3]) : "r"(addr));
}
__device__ __forceinline__ uint32_t pack_bf(float x, float y) {
    __nv_bfloat162 p = __floats2bfloat162_rn(x, y);
    return *(uint32_t*)&p;
}

// =====================================================================
// Prep kernels
// =====================================================================
__global__ void prep_h0(const float4* __restrict__ Hd) {
    int i = blockIdx.x * 1024 + threadIdx.x;
    if (i < B_ * H_ / 4) {
        float4 v = Hd[i];
        *(uint2*)&g_h0[i * 4] = make_uint2(pack_bf(v.x, v.y), pack_bf(v.z, v.w));
    }
}
// W blobs: [ct 16][phase 2][chunk 4] of 96 rows x 128 k bf16 (row-major 256B rows)
__global__ void prep_w(const float* __restrict__ Whh, const float* __restrict__ Wih) {
    size_t idx = (size_t)blockIdx.x * 1024 + threadIdx.x;
    if (idx >= (size_t)16 * 2 * 4 * 96 * 128) return;
    int k  = (int)(idx & 127);
    size_t i2 = idx >> 7;
    int r = (int)(i2 % 96); size_t i3 = i2 / 96;
    int c = (int)(i3 & 3);
    size_t i4 = i3 >> 2;
    int p  = (int)(i4 & 1);
    int ct = (int)(i4 >> 1);
    const float* W = p ? Wih : Whh;
    int grow = (r >> 5) * 512 + ct * 32 + (r & 31);
    float v = W[(size_t)grow * 512 + c * 128 + k];
    size_t blob = ((size_t)(ct * 2 + p) * 4 + c) * 24576;
    *(__nv_bfloat16*)(g_wblob + blob + (size_t)r * 256 + k * 2) = __float2bfloat16(v);
}

// =====================================================================
// xproj: g_xp[(m*16+ct)*96 + col] = x[m,:] @ Wih_tile(ct)[col,:]^T  (fp32 out)
// Tile 64 rows x 96 cols, K=512 (4 chunks of 128). 128 threads, 2 CTAs/SM.
// GRID SWAPPED vs R8: ct = blockIdx.x (fast axis) so the 16 ct-CTAs of one
// m-tile are schedule-adjacent -> A tile served from L2, reps read ONCE.
// =====================================================================
#define XSTG 43520     // stage bytes: A 64x272 + B 96x272

__global__ void __launch_bounds__(128, 2)
xproj_kernel(const float* __restrict__ reps) {
    extern __shared__ unsigned char dsm[];
    const uint32_t smb = (uint32_t)__cvta_generic_to_shared(dsm);

    const int m0 = blockIdx.y * 64;          // SWAPPED
    const int ct = blockIdx.x;               // SWAPPED
    const int tid = threadIdx.x;
    const int l   = tid & 31;
    const int w   = tid >> 5;                 // 4 warps, strip rows 16w..16w+15
    const int g   = l >> 2;
    const int tg  = l & 3;
    const uint32_t loff = (uint32_t)((((l >> 3) & 1) * 8 + (l & 7)) * 272 + (l >> 4) * 16);

    // A slots: 2048 float4 per chunk / 128 thr = 16
    int arow[16], ac4[16];
#pragma unroll
    for (int i = 0; i < 16; i++) {
        int u = tid + i * 128;
        arow[i] = u >> 5; ac4[i] = (u & 31) * 4;
    }
    // B slots: 1536 units / 128 thr = 12
    const unsigned char* blobs = g_wblob + ((size_t)(ct * 2 + 1) * 4) * 24576;  // phase 1 (Wih)
    uint32_t bdst[12], bsrc[12];
#pragma unroll
    for (int i = 0; i < 12; i++) {
        int u = tid + i * 128;
        bdst[i] = (uint32_t)(17408 + (u >> 4) * 272 + (u & 15) * 16);
        bsrc[i] = (uint32_t)u * 16;
    }

    auto issueB = [&](int c) {
        uint32_t base = smb + (uint32_t)(c & 1) * XSTG;
        const unsigned char* blob = blobs + (size_t)c * 24576;
#pragma unroll
        for (int i = 0; i < 12; i++) cpa16(base + bdst[i], blob + bsrc[i]);
        cp_commit();
    };
    float4 ra[16];
    auto ldgA = [&](int c) {
#pragma unroll
        for (int i = 0; i < 16; i++)
            ra[i] = *(const float4*)&reps[(size_t)(m0 + arow[i]) * 512 + c * 128 + ac4[i]];
    };
    auto stsA = [&](int c) {
        unsigned char* dst = dsm + (size_t)(c & 1) * XSTG;
#pragma unroll
        for (int i = 0; i < 16; i++) {
            float4 v = ra[i];
            *(uint2*)(dst + arow[i] * 272 + ac4[i] * 2) =
                make_uint2(pack_bf(v.x, v.y), pack_bf(v.z, v.w));
        }
    };

    float acc[12][4];
#pragma unroll
    for (int i = 0; i < 12; i++)
#pragma unroll
        for (int j = 0; j < 4; j++) acc[i][j] = 0.0f;

    ldgA(0);
    issueB(0); issueB(1);
    for (int c = 0; c < 4; c++) {
        stsA(c);
        if (c < 3) ldgA(c + 1);
        if (c < 3) cp_wait<1>(); else cp_wait<0>();
        __syncthreads();
        uint32_t Ab = smb + (uint32_t)(c & 1) * XSTG + (uint32_t)(w * 16) * 272 + loff;
        uint32_t Bb = smb + (uint32_t)(c & 1) * XSTG + 17408 + loff;
#pragma unroll
        for (int kk = 0; kk < 8; kk++) {
            uint32_t kb = (uint32_t)kk * 32;
            uint32_t a[4]; ldsm4(a, Ab + kb);
#pragma unroll
            for (int q = 0; q < 6; q++) {
                uint32_t r4[4]; ldsm4(r4, Bb + (uint32_t)(q * 16) * 272 + kb);
                uint32_t b0[2] = { r4[0], r4[2] }, b1[2] = { r4[1], r4[3] };
                mma16(acc[2 * q], a, b0);
                mma16(acc[2 * q + 1], a, b1);
            }
        }
        __syncthreads();
        if (c < 2) issueB(c + 2);
    }

    // write fp32 results
#pragma unroll
    for (int f = 0; f < 12; f++) {
        int col = 8 * f + 2 * tg;
        size_t m = (size_t)(m0 + 16 * w + g);
        *(float2*)&g_xp[(m * 16 + ct) * 96 + col] = make_float2(acc[f][0], acc[f][1]);
        *(float2*)&g_xp[((m + 8) * 16 + ct) * 96 + col] = make_float2(acc[f][2], acc[f][3]);
    }
}

// =====================================================================
// Persistent GRU (serial K=512 h-GEMM only) + fused Wa-prep CTAs.
// GRU: 256 CTAs = 16 batch-groups(64 rows) x 16 col-tiles(32 hcols = 96 gate rows).
// 128 threads, 2 CTAs/SM. 16 barrier groups.
// xp tile (64x96 fp32) cp.async-prefetched per step. In-register gate epilogue.
// prep CTAs (bid>=256): Wa fp32 -> bf16 + row sums.
// =====================================================================
#define GSTG   43520
#define XPOFF  87040   // xp region byte offset (64 x 100 fp32)

__global__ void __launch_bounds__(128, 2)
gru_kernel(const float* __restrict__ hidden,
           const float* __restrict__ bhh,
           const float* __restrict__ bih,
           const float* __restrict__ Wa) {
    const int cta = blockIdx.x;
    const int tid = threadIdx.x;

    if (cta >= GRU_CTAS) {
        // ---------- fused Wa prep ----------
        int wp = tid >> 5, lane = tid & 31;
        for (int gw = (cta - GRU_CTAS) * 4 + wp; gw < NU * 512; gw += PREP_CTAS * 4) {
            const float* src = Wa + (size_t)gw * 512;
            __nv_bfloat16* dst = g_wabf + (size_t)gw * 512;
            float s = 0.0f;
#pragma unroll
            for (int i = 0; i < 4; i++) {
                float4 v = *(const float4*)&src[(lane + i * 32) * 4];
                s += v.x + v.y + v.z + v.w;
                *(uint2*)&dst[(lane + i * 32) * 4] =
                    make_uint2(pack_bf(v.x, v.y), pack_bf(v.z, v.w));
            }
#pragma unroll
            for (int off = 16; off > 0; off >>= 1) s += __shfl_xor_sync(0xffffffffu, s, off);
            if (lane == 0) g_R[gw] = s;
        }
        return;
    }

    // ---------- GRU ----------
    extern __shared__ unsigned char dsm[];
    const uint32_t smb = (uint32_t)__cvta_generic_to_shared(dsm);
    __shared__ float sb[128];
    float* xp = (float*)(dsm + XPOFF);

    const int bg   = cta >> 4;
    const int ct   = cta & 15;
    const int b0   = bg * 64;
    const int col0 = ct * 32;
    const int l    = tid & 31;
    const int w    = tid >> 5;
    const int g    = l >> 2;
    const int tg   = l & 3;
    const uint32_t loff = (uint32_t)((((l >> 3) & 1) * 8 + (l & 7)) * 272 + (l >> 4) * 16);

    // loader slots
    int arow[8], aku[8];
#pragma unroll
    for (int i = 0; i < 8; i++) {
        int u = tid + i * 128;
        arow[i] = u >> 4; aku[i] = u & 15;
    }
    uint32_t bdst[12], bsrc[12];
#pragma unroll
    for (int i = 0; i < 12; i++) {
        int u = tid + i * 128;
        bdst[i] = (uint32_t)(17408 + (u >> 4) * 272 + (u & 15) * 16);
        bsrc[i] = (uint32_t)u * 16;
    }
    int xr_[12], xc_[12];
#pragma unroll
    for (int i = 0; i < 12; i++) {
        int u = tid + i * 128;              // 1536 units (64 rows x 24)
        xr_[i] = u / 24; xc_[i] = u % 24;
    }
    const unsigned char* blobs = g_wblob + ((size_t)(ct * 2 + 0) * 4) * 24576;  // phase 0 (Whh)

    if (tid < 32) {
        int jc = col0 + tid;
        sb[tid]      = bih[jc] + bhh[jc];
        sb[32 + tid] = bih[512 + jc] + bhh[512 + jc];
        sb[64 + tid] = bhh[1024 + jc];
        sb[96 + tid] = bih[1024 + jc];
    }
    __syncthreads();

    unsigned gen = *((volatile unsigned*)&g_gbarg[bg]);

    for (int t = 0; t < S_; t++) {
        // xp prefetch (group 0)
#pragma unroll
        for (int i = 0; i < 12; i++) {
            size_t m = (size_t)(b0 + xr_[i]) * S_ + t;
            cpa16(smb + XPOFF + (uint32_t)(xr_[i] * 400 + xc_[i] * 16),
                  g_xp + (m * 16 + ct) * 96 + xc_[i] * 4);
        }
        cp_commit();

        auto issue = [&](int c) {
            uint32_t base = smb + (uint32_t)(c & 1) * GSTG;
            if (t == 0) {
#pragma unroll
                for (int i = 0; i < 8; i++)
                    cpa16(base + (uint32_t)(arow[i] * 272 + aku[i] * 16),
                          g_h0 + (size_t)(b0 + arow[i]) * 512 + c * 128 + aku[i] * 8);
            } else {
#pragma unroll
                for (int i = 0; i < 8; i++)
                    cpa16(base + (uint32_t)(arow[i] * 272 + aku[i] * 16),
                          g_obf + ((size_t)(b0 + arow[i]) * S_ + (t - 1)) * 512 + c * 128 + aku[i] * 8);
            }
            const unsigned char* blob = blobs + (size_t)c * 24576;
#pragma unroll
            for (int i = 0; i < 12; i++) cpa16(base + bdst[i], blob + bsrc[i]);
            cp_commit();
        };

        float acc[12][4];
#pragma unroll
        for (int i = 0; i < 12; i++)
#pragma unroll
            for (int j = 0; j < 4; j++) acc[i][j] = 0.0f;

        issue(0); issue(1);
        for (int c = 0; c < 4; c++) {
            if (c < 3) cp_wait<1>(); else cp_wait<0>();
            __syncthreads();
            uint32_t Ab = smb + (uint32_t)(c & 1) * GSTG + (uint32_t)(16 * w) * 272 + loff;
            uint32_t Bb = smb + (uint32_t)(c & 1) * GSTG + 17408 + loff;
#pragma unroll
            for (int kk = 0; kk < 8; kk++) {
                uint32_t kb = (uint32_t)kk * 32;
                uint32_t a[4]; ldsm4(a, Ab + kb);
#pragma unroll
                for (int q = 0; q < 6; q++) {
                    uint32_t r4[4]; ldsm4(r4, Bb + (uint32_t)(q * 16) * 272 + kb);
                    uint32_t b0f[2] = { r4[0], r4[2] }, b1f[2] = { r4[1], r4[3] };
                    mma16(acc[2 * q], a, b0f);
                    mma16(acc[2 * q + 1], a, b1f);
                }
            }
            __syncthreads();
            if (c < 2) issue(c + 2);
        }

        // ---- in-register gates (frags: 0-3 r, 4-7 z, 8-11 nh; x-part from xp smem) ----
#pragma unroll
        for (int half = 0; half < 2; half++) {
            int lrow = 16 * w + g + half * 8;
            int rr = b0 + lrow;
            const float* hp = (t == 0)
                ? hidden + (size_t)rr * 512 + col0
                : g_out + ((size_t)rr * S_ + (t - 1)) * 512 + col0;
            float* op = g_out + ((size_t)rr * S_ + t) * 512 + col0;
            __nv_bfloat16* ob = g_obf + ((size_t)rr * S_ + t) * 512 + col0;
            const float* xrow = xp + lrow * 100;
#pragma unroll
            for (int q = 0; q < 4; q++) {
                int j = 8 * q + 2 * tg;
                float2 hv  = *(const float2*)(hp + j);
                float2 xr2 = *(const float2*)(xrow + j);
                float2 xz2 = *(const float2*)(xrow + 32 + j);
                float2 xn2 = *(const float2*)(xrow + 64 + j);
                float r0 = sigf(xr2.x + acc[q][2*half + 0] + sb[j]);
                float r1 = sigf(xr2.y + acc[q][2*half + 1] + sb[j + 1]);
                float z0 = sigf(xz2.x + acc[4 + q][2*half + 0] + sb[32 + j]);
                float z1 = sigf(xz2.y + acc[4 + q][2*half + 1] + sb[32 + j + 1]);
                float n0 = tanhc((xn2.x + sb[96 + j])     + r0 * (acc[8 + q][2*half + 0] + sb[64 + j]));
                float n1 = tanhc((xn2.y + sb[96 + j + 1]) + r1 * (acc[8 + q][2*half + 1] + sb[64 + j + 1]));
                float o0 = (1.0f - z0) * n0 + z0 * hv.x;
                float o1 = (1.0f - z1) * n1 + z1 * hv.y;
                *(float2*)(op + j) = make_float2(o0, o1);
                *(uint32_t*)(ob + j) = pack_bf(o0, o1);
            }
        }

        // ---- group barrier (16 CTAs sharing this batch group) ----
        if (t < S_ - 1) {
            __syncthreads();
            if (tid == 0) {
                unsigned target = gen + 1;
                __threadfence();
                if (atomicAdd(&g_gbarc[bg], 1u) == 15u) {
                    g_gbarc[bg] = 0;
                    __threadfence();
                    atomicExch(&g_gbarg[bg], target);
                } else {
                    while (*((volatile unsigned*)&g_gbarg[bg]) != target) __nanosleep(32);
                    __threadfence();
                }
                gen = target;
            }
            __syncthreads();
        }
    }
}

// =====================================================================
// Attention: A = g_obf (bf16), masked rows fixed up in smem.
// Wa bf16 streamed 4-deep. 8 o-passes of 64 cols.
// =====================================================================
#define A_STRIDE 1040
#define B_STRIDE 144
#define B_STG    9216
#define ATTN_SM  (133120 + 4 * B_STG)

__global__ void __launch_bounds__(256)
attn_kernel(const float* __restrict__ reps,
            const int*   __restrict__ counts,
            const int*   __restrict__ users,
            const float* __restrict__ ba,
            const float* __restrict__ Ws,
            const float* __restrict__ bs,
            float*       __restrict__ outp) {
    extern __shared__ unsigned char dsm[];
    const uint32_t smb = (uint32_t)__cvta_generic_to_shared(dsm);
    __shared__ float scores_s[128];
    __shared__ float wts[S_];
    __shared__ float inv_s;

    const int b   = blockIdx.x;
    const int u   = users[b];
    const int cnt = counts[b];
    const size_t ub = (size_t)u * 512;
    const __nv_bfloat16* wab = g_wabf + (size_t)u * 512 * 512;

    const int tid = threadIdx.x;
    const int l   = tid & 31;
    const int w   = tid >> 5;
    const int g   = l >> 2;
    const int tg  = l & 3;
    const uint32_t loffA = (uint32_t)((((l >> 3) & 1) * 8 + (l & 7)) * A_STRIDE + (l >> 4) * 16);
    const uint32_t loffB = (uint32_t)((((l >> 3) & 1) * 8 + (l & 7)) * B_STRIDE + (l >> 4) * 16);

    int rB[2], kuB[2];
#pragma unroll
    for (int i = 0; i < 2; i++) {
        int uu = tid + i * 256;
        rB[i] = uu >> 3; kuB[i] = uu & 7;
    }
    auto issueB = [&](int gidx) {
        int pass = gidx >> 3, c = gidx & 7;
        uint32_t base = smb + 133120 + (uint32_t)(gidx & 3) * B_STG;
#pragma unroll
        for (int i = 0; i < 2; i++)
            cpa16(base + (uint32_t)(rB[i] * B_STRIDE + kuB[i] * 16),
                  wab + (size_t)(pass * 64 + rB[i]) * 512 + c * 64 + kuB[i] * 8);
        cp_commit();
    };

    issueB(0); issueB(1); issueB(2);

#pragma unroll
    for (int i = 0; i < 25; i++) {
        int uu = tid + i * 256;
        int row = uu >> 6, cu = uu & 63;
        uint4 v = *(const uint4*)&g_obf[((size_t)b * S_ + row) * 512 + cu * 8];
        *(uint4*)(dsm + row * A_STRIDE + cu * 16) = v;
    }
    __syncthreads();
    {
        int nwords = (S_ - cnt) * 256;
        for (int widx = tid; widx < nwords; widx += 256) {
            int row = cnt + (widx >> 8), cw = widx & 255;
            uint32_t* p = (uint32_t*)(dsm + row * A_STRIDE + cw * 4);
            uint32_t pv = *p;
            __nv_bfloat162 bv = *(__nv_bfloat162*)&pv;
            float vx = (__bfloat162float(bv.x) - 1e6f) + 1e6f;
            float vy = (__bfloat162float(bv.y) - 1e6f) + 1e6f;
            *p = pack_bf(vx, vy);
        }
    }
    __syncthreads();

    const bool m0 = (16 * w + g >= cnt);
    const bool m1 = (16 * w + 8 + g >= cnt);
    float pr0 = 0.0f, pr1 = 0.0f;

    for (int pass = 0; pass < 8; pass++) {
        float acc[8][4];
#pragma unroll
        for (int i = 0; i < 8; i++)
#pragma unroll
            for (int j = 0; j < 4; j++) acc[i][j] = 0.0f;

        for (int c = 0; c < 8; c++) {
            int gidx = pass * 8 + c;
            if (gidx < 62) cp_wait<2>();
            else if (gidx == 62) cp_wait<1>();
            else cp_wait<0>();
            __syncthreads();
            uint32_t Ab = smb + (uint32_t)(w * 16) * A_STRIDE + loffA + (uint32_t)(c * 64) * 2;
            uint32_t Bb = smb + 133120 + (uint32_t)(gidx & 3) * B_STG + loffB;
#pragma unroll
            for (int kk = 0; kk < 4; kk++) {
                uint32_t a[4]; ldsm4(a, Ab + (uint32_t)kk * 32);
#pragma unroll
                for (int q = 0; q < 4; q++) {
                    uint32_t r4[4];
                    ldsm4(r4, Bb + (uint32_t)(q * 16) * B_STRIDE + (uint32_t)kk * 32);
                    uint32_t b0f[2] = { r4[0], r4[2] }, b1f[2] = { r4[1], r4[3] };
                    mma16(acc[2 * q], a, b0f);
                    mma16(acc[2 * q + 1], a, b1f);
                }
            }
            __syncthreads();
            if (gidx + 3 < 64) issueB(gidx + 3);
        }

        int o0 = pass * 64;
#pragma unroll
        for (int f = 0; f < 8; f++) {
            int col = o0 + 8 * f + 2 * tg;
            float2 bav = *(const float2*)&ba[ub + col];
            float2 wsv = *(const float2*)&Ws[ub + col];
            float2 Rv  = *(const float2*)&g_R[ub + col];
            float C0 = bav.x - 1e6f * Rv.x;
            float C1 = bav.y - 1e6f * Rv.y;
            pr0 += tanhc(acc[f][0] + (m0 ? C0 : bav.x)) * wsv.x
                 + tanhc(acc[f][1] + (m0 ? C1 : bav.y)) * wsv.y;
            pr1 += tanhc(acc[f][2] + (m1 ? C0 : bav.x)) * wsv.x
                 + tanhc(acc[f][3] + (m1 ? C1 : bav.y)) * wsv.y;
        }
    }

    pr0 += __shfl_xor_sync(0xffffffffu, pr0, 1);
    pr0 += __shfl_xor_sync(0xffffffffu, pr0, 2);
    pr1 += __shfl_xor_sync(0xffffffffu, pr1, 1);
    pr1 += __shfl_xor_sync(0xffffffffu, pr1, 2);
    float bsu = bs[u];
    if (tg == 0) {
        scores_s[16 * w + g]     = pr0 + bsu;
        scores_s[16 * w + 8 + g] = pr1 + bsu;
    }
    __syncthreads();

    if (w == 0) {
        float m = -1e30f;
        for (int s = l; s < S_; s += 32) m = fmaxf(m, scores_s[s]);
#pragma unroll
        for (int off = 16; off > 0; off >>= 1) m = fmaxf(m, __shfl_xor_sync(0xffffffffu, m, off));
        float sum = 0.0f;
        for (int s = l; s < S_; s += 32) {
            float e = __expf(scores_s[s] - m);
            wts[s] = e;
            sum += e;
        }
#pragma unroll
        for (int off = 16; off > 0; off >>= 1) sum += __shfl_xor_sync(0xffffffffu, sum, off);
        if (l == 0) inv_s = 1.0f / sum;
    }
    __syncthreads();

    const float* rb = reps + (size_t)b * S_ * 512;
    float acc0 = 0.0f, acc1 = 0.0f;
    for (int s = 0; s < S_; s++) {
        float wv = wts[s];
        acc0 += wv * rb[(size_t)s * 512 + tid];
        acc1 += wv * rb[(size_t)s * 512 + 256 + tid];
    }
    float inv = inv_s;
    outp[(size_t)b * 512 + tid]       = acc0 * inv;
    outp[(size_t)b * 512 + 256 + tid] = acc1 * inv;
}

// =====================================================================
extern "C" void kernel_launch(void* const* d_in, const int* in_sizes, int n_in,
                              void* d_out, int out_size) {
    (void)in_sizes; (void)n_in; (void)out_size;
    const float* reps   = (const float*)d_in[0];
    const float* hidden = (const float*)d_in[1];
    const int*   counts = (const int*)  d_in[2];
    const int*   users  = (const int*)  d_in[3];
    const float* Wih    = (const float*)d_in[4];
    const float* Whh    = (const float*)d_in[5];
    const float* bih    = (const float*)d_in[6];
    const float* bhh    = (const float*)d_in[7];
    const float* Wa     = (const float*)d_in[8];
    const float* ba     = (const float*)d_in[9];
    const float* Wsc    = (const float*)d_in[10];
    const float* bsc    = (const float*)d_in[11];
    float* outp = (float*)d_out;

    cudaFuncSetAttribute(xproj_kernel, cudaFuncAttributeMaxDynamicSharedMemorySize, 2 * XSTG);
    cudaFuncSetAttribute(gru_kernel, cudaFuncAttributeMaxDynamicSharedMemorySize, XPOFF + 25600);
    cudaFuncSetAttribute(attn_kernel, cudaFuncAttributeMaxDynamicSharedMemorySize, ATTN_SM);

    prep_h0<<<128, 1024>>>((const float4*)hidden);
    prep_w<<<1536, 1024>>>(Whh, Wih);
    xproj_kernel<<<dim3(16, 1600), 128, 2 * XSTG>>>(reps);
    gru_kernel<<<GRU_CTAS + PREP_CTAS, 128, XPOFF + 25600>>>(hidden, bhh, bih, Wa);
    attn_kernel<<<B_, 256, ATTN_SM>>>(reps, counts, users, ba, Wsc, bsc, outp);
}